// round 5
// baseline (speedup 1.0000x reference)
#include <cuda_runtime.h>
#include <cuda_bf16.h>

// Problem constants (fixed by the reference):
//   VOXEL_SIZE = (0.16, 0.16, 4.0), PC_RANGE = (0, -39.68, -3, 69.12, 39.68, 1)
//   GRID = (432, 496, 1), MAX_VOX = 160000, C = 4
#define GX 432
#define GY 496
#define GZ 1
#define TOTAL_CELLS (GX * GY * GZ)   // 214272
#define MAX_VOX 160000
#define CPB 1024                     // cells per write block
#define NBLK ((TOTAL_CELLS + CPB - 1) / CPB)  // 210

// Scratch (allocation-free rule: __device__ globals, zero-initialized at load).
// Invariant: zero at entry to every kernel_launch call; k_write restores it
// after reading, so graph replays are deterministic.
__device__ float4 g_vsum[TOTAL_CELLS];
__device__ int    g_vcnt[TOTAL_CELLS];
__device__ int    g_bocc[NBLK * 32];  // per-scan-block occupied-cell counts,
                                      // padded to one 128B line per counter
__device__ int    g_done;             // tail-reset arrivals counter

// ---------------------------------------------------------------------------
// 1. Accumulate: per point, find cell, one v4 float REDG + one counted int
//    atomic. First touch of a cell (old==0) bumps that scan-block's occupancy
//    counter, so the prefix source is ready when k_write starts (stream order).
//    Cell computation matches jnp float32 exactly (IEEE rn division + floor).
// ---------------------------------------------------------------------------
__global__ void k_acc(const float* __restrict__ in, int N, int P) {
    int i = blockIdx.x * blockDim.x + threadIdx.x;
    if (i >= P) return;
    int b = i / N;
    int n = i - b * N;
    const float* p = in + (size_t)b * 4 * (size_t)N + n;
    float x = p[0];
    float y = p[(size_t)N];
    float z = p[2 * (size_t)N];
    float w = p[3 * (size_t)N];

    float fx = floorf(__fdiv_rn(x - 0.0f,   0.16f));
    float fy = floorf(__fdiv_rn(y + 39.68f, 0.16f));
    float fz = floorf(__fdiv_rn(z + 3.0f,   4.0f));
    if (fx < 0.0f || fy < 0.0f || fz < 0.0f) return;
    int cx = (int)fx, cy = (int)fy, cz = (int)fz;
    if (cx >= GX || cy >= GY || cz >= GZ) return;

    int cell = (cz * GY + cy) * GX + cx;

    float4* vp = &g_vsum[cell];
    asm volatile("red.global.add.v4.f32 [%0], {%1, %2, %3, %4};"
                 :: "l"(vp), "f"(x), "f"(y), "f"(z), "f"(w) : "memory");
    int old = atomicAdd(&g_vcnt[cell], 1);
    if (old == 0)
        atomicAdd(&g_bocc[(cell >> 10) * 32], 1);  // first touch of this cell
}

// ---------------------------------------------------------------------------
// 2. Fused write: exclusive block prefix from g_bocc (masked warp sum — no
//    inter-block waiting), block-local flag scan -> seg id, write mean,
//    reset scratch. Last-finishing block resets g_bocc/g_done for the next
//    replay; all blocks consumed their g_bocc reads before arriving.
// ---------------------------------------------------------------------------
__global__ void k_write(float4* __restrict__ out4) {
    __shared__ int wsum[32];
    __shared__ int s_excl;
    int b = blockIdx.x;
    int t = threadIdx.x;
    int lane = t & 31;
    int wid = t >> 5;
    int cell = b * CPB + t;
    int cnt = (cell < TOTAL_CELLS) ? g_vcnt[cell] : 0;
    int flag = cnt > 0;

    // Exclusive inter-block prefix: sum of g_bocc[i] for i < b (warp 0).
    if (wid == 0) {
        int acc = 0;
        for (int i = lane; i < b; i += 32) acc += g_bocc[i * 32];
        #pragma unroll
        for (int o = 16; o > 0; o >>= 1)
            acc += __shfl_xor_sync(0xFFFFFFFFu, acc, o);
        if (lane == 0) s_excl = acc;
    }

    // Inclusive warp scan of flags
    int v = flag;
    #pragma unroll
    for (int o = 1; o < 32; o <<= 1) {
        int nv = __shfl_up_sync(0xFFFFFFFFu, v, o);
        if (lane >= o) v += nv;
    }
    if (lane == 31) wsum[wid] = v;
    __syncthreads();
    if (wid == 0) {
        int w = wsum[lane];
        #pragma unroll
        for (int o = 1; o < 32; o <<= 1) {
            int nw = __shfl_up_sync(0xFFFFFFFFu, w, o);
            if (lane >= o) w += nw;
        }
        wsum[lane] = w;  // inclusive warp totals
    }
    __syncthreads();
    int excl_blk = s_excl;
    int block_agg = wsum[31];

    // Write means
    if (flag) {
        int seg = excl_blk + (v - flag) + (wid > 0 ? wsum[wid - 1] : 0);
        if (seg < MAX_VOX) {
            float fc = (float)cnt;
            float4 s = g_vsum[cell];
            float4 r;
            r.x = __fdiv_rn(s.x, fc);
            r.y = __fdiv_rn(s.y, fc);
            r.z = __fdiv_rn(s.z, fc);
            r.w = __fdiv_rn(s.w, fc);
            out4[seg] = r;
        }
    }

    // Reset per-cell scratch (thread<->cell is 1:1; reads above are by the
    // same thread, so program order suffices).
    const float4 z4 = make_float4(0.f, 0.f, 0.f, 0.f);
    if (cell < TOTAL_CELLS) {
        g_vcnt[cell] = 0;
        g_vsum[cell] = z4;
    }

    // Exact tail zeroing: the last block knows the global occupied total.
    // (For this input total ~209k > MAX_VOX, so this loop does no work.)
    if (b == NBLK - 1) {
        int total = excl_blk + block_agg;
        for (int j = total + t; j < MAX_VOX; j += CPB) out4[j] = z4;
    }

    // Tail reset of g_bocc by the last block to arrive. Every block passed
    // this barrier only after its g_bocc loads were consumed into s_excl,
    // so the resetter cannot clobber a pending read.
    __syncthreads();
    if (t == 0) {
        __threadfence();
        int done = atomicAdd(&g_done, 1);
        if (done == NBLK - 1) {
            for (int i = 0; i < NBLK; i++) g_bocc[i * 32] = 0;
            __threadfence();
            g_done = 0;
        }
    }
}

// ---------------------------------------------------------------------------
extern "C" void kernel_launch(void* const* d_in, const int* in_sizes, int n_in,
                              void* d_out, int out_size) {
    const float* in = (const float*)d_in[0];
    float4* out4 = (float4*)d_out;
    int total = in_sizes[0];       // B * C * N = 4 * 4 * 200000
    int N = total / 16;            // points per batch (B=4, C=4)
    int P = total / 4;             // total points

    k_acc<<<(P + 255) / 256, 256>>>(in, N, P);
    k_write<<<NBLK, CPB>>>(out4);
}